// round 15
// baseline (speedup 1.0000x reference)
#include <cuda_runtime.h>
#include <cuda_fp16.h>
#include <math.h>
#include <stdint.h>

#define NB 2
#define NCH 512
#define NSP 4096
#define NGROUPS 32
#define GELEMS 65536                       // 16 * 4096 per (b,g)
#define BCH_N ((size_t)NCH * NSP)          // 2097152
#define QK_N  ((size_t)NSP * 1024)         // qkT per-batch stride
#define ATT_N ((size_t)NSP * NSP)          // 16777216

// ---------------- scratch (static device globals; no allocations) ------------
__device__ __half g_hT[NB * NSP * NCH];        // [b][n][c]
__device__ __half g_w[4][NCH * NCH];           // wq, wk, wv, wo (wq,wk adjacent!)
__device__ float  g_bqk[1024];                 // concat(bq, bk)
__device__ __half g_qkT[NB * NSP * 1024];      // [b][n][q:0..511 | k:512..1023]
__device__ __half g_v[NB * NCH * NSP];         // [b][c][n]
__device__ float  g_S[(size_t)NB * NSP * NSP];        // 134 MB
__device__ __half g_attn[(size_t)NB * NSP * NSP];     // [b][i][j]
__device__ __half g_oT[NB * NSP * NCH];        // [b][i][c]
__device__ float  g_stats[NB * NGROUPS * 2];

// ---------------- PTX helpers ------------------------------------------------
__device__ __forceinline__ uint32_t smem_u32(const void* p) {
    uint32_t a;
    asm("{ .reg .u64 t; cvta.to.shared.u64 t, %1; cvt.u32.u64 %0, t; }" : "=r"(a) : "l"(p));
    return a;
}
__device__ __forceinline__ void cpa16(uint32_t dst, const void* src) {
    asm volatile("cp.async.cg.shared.global [%0], [%1], 16;" :: "r"(dst), "l"(src));
}
#define CP_COMMIT() asm volatile("cp.async.commit_group;")
#define CP_WAIT(n)  asm volatile("cp.async.wait_group %0;" :: "n"(n) : "memory")

#define LDSM4(r, a) \
    asm volatile("ldmatrix.sync.aligned.m8n8.x4.shared.b16 {%0,%1,%2,%3}, [%4];" \
        : "=r"((r)[0]), "=r"((r)[1]), "=r"((r)[2]), "=r"((r)[3]) : "r"(a))
#define MMA_F16(d, a, b) \
    asm volatile("mma.sync.aligned.m16n8k16.row.col.f32.f16.f16.f32 " \
        "{%0,%1,%2,%3}, {%4,%5,%6,%7}, {%8,%9}, {%0,%1,%2,%3};" \
        : "+f"((d)[0]), "+f"((d)[1]), "+f"((d)[2]), "+f"((d)[3]) \
        : "r"((a)[0]), "r"((a)[1]), "r"((a)[2]), "r"((a)[3]), \
          "r"((b)[0]), "r"((b)[1]))

// ---------------- GroupNorm stats --------------------------------------------
__global__ void gn_stats_kernel(const float* __restrict__ x) {
    __shared__ float sh_s[256], sh_ss[256];
    const int bg = blockIdx.x;
    const float* p = x + (size_t)bg * GELEMS;
    float s = 0.f, ss = 0.f;
    for (int i = threadIdx.x * 4; i < GELEMS; i += 256 * 4) {
        float4 v = *(const float4*)&p[i];
        s  += v.x + v.y + v.z + v.w;
        ss += v.x * v.x + v.y * v.y + v.z * v.z + v.w * v.w;
    }
    sh_s[threadIdx.x] = s; sh_ss[threadIdx.x] = ss;
    __syncthreads();
    for (int st = 128; st > 0; st >>= 1) {
        if (threadIdx.x < st) {
            sh_s[threadIdx.x]  += sh_s[threadIdx.x + st];
            sh_ss[threadIdx.x] += sh_ss[threadIdx.x + st];
        }
        __syncthreads();
    }
    if (threadIdx.x == 0) {
        float mean = sh_s[0] * (1.f / GELEMS);
        float var  = sh_ss[0] * (1.f / GELEMS) - mean * mean;
        g_stats[bg * 2 + 0] = mean;
        g_stats[bg * 2 + 1] = rsqrtf(var + 1e-6f);
    }
}

// ------------- GroupNorm + transpose + fp16 convert --------------------------
__global__ void gn_tr_kernel(const float* __restrict__ x,
                             const float* __restrict__ gamma,
                             const float* __restrict__ beta) {
    __shared__ float t[32][33];
    const int b  = blockIdx.z;
    const int c0 = blockIdx.y * 32;
    const int n0 = blockIdx.x * 32;
    const float* xb = x + (size_t)b * BCH_N;
    const int tx = threadIdx.x, ty = threadIdx.y;
#pragma unroll
    for (int r = 0; r < 4; r++) {
        int c = c0 + ty + r * 8;
        int bg = b * NGROUPS + (c >> 4);
        float mean = g_stats[bg * 2 + 0], rstd = g_stats[bg * 2 + 1];
        float ga = gamma[c] * rstd;
        float be = beta[c] - mean * ga;
        t[ty + r * 8][tx] = xb[(size_t)c * NSP + n0 + tx] * ga + be;
    }
    __syncthreads();
#pragma unroll
    for (int r = 0; r < 4; r++) {
        int n = n0 + ty + r * 8;
        int c = c0 + tx;
        g_hT[((size_t)b * NSP + n) * NCH + c] = __float2half(t[tx][ty + r * 8]);
    }
}

// -------- fp32 -> fp16 convert, all 4 weights + qk bias concat ---------------
__global__ void cvt4_kernel(const float* __restrict__ a, const float* __restrict__ b,
                            const float* __restrict__ c, const float* __restrict__ d,
                            const float* __restrict__ bq, const float* __restrict__ bk,
                            __half* __restrict__ dst) {
    const int WN = NCH * NCH;
    int i = blockIdx.x * blockDim.x + threadIdx.x;
    dst[0 * WN + i] = __float2half(a[i]);
    dst[1 * WN + i] = __float2half(b[i]);
    dst[2 * WN + i] = __float2half(c[i]);
    dst[3 * WN + i] = __float2half(d[i]);
    if (i < NCH) {
        g_bqk[i] = bq[i];
        g_bqk[NCH + i] = bk[i];
    }
}

// ---------------- softmax row -> fp16 ----------------------------------------
__global__ void softmax_kernel(const float* __restrict__ S) {
    __shared__ float row[NSP];
    __shared__ float red[256];
    const size_t r = blockIdx.x;
    const float* p = S + r * NSP;
    const int tid = threadIdx.x;

    float m = -1e30f;
    for (int i = tid; i < NSP; i += 256) {
        float v = p[i];
        row[i] = v;
        m = fmaxf(m, v);
    }
    red[tid] = m; __syncthreads();
    for (int st = 128; st > 0; st >>= 1) {
        if (tid < st) red[tid] = fmaxf(red[tid], red[tid + st]);
        __syncthreads();
    }
    m = red[0]; __syncthreads();

    float s = 0.f;
    for (int i = tid; i < NSP; i += 256) {
        float e = __expf(row[i] - m);
        row[i] = e;
        s += e;
    }
    red[tid] = s; __syncthreads();
    for (int st = 128; st > 0; st >>= 1) {
        if (tid < st) red[tid] += red[tid + st];
        __syncthreads();
    }
    float inv = 1.f / red[0];
    size_t base = r * NSP;
    for (int i = tid; i < NSP; i += 256)
        g_attn[base + i] = __float2half(row[i] * inv);
}

// ---------------- fp16 GEMM via mma.sync (HMMA) ------------------------------
// C[M,N] = alpha * A[M,K] . B[N,K]^T  (+ bias) (+ resid)
// CTA tile 128x256x32, 8 warps (2x4), warp tile 64x64, 3-stage cp.async,
// fragment double-buffer over k16 groups (hides ldmatrix latency).
// SMEM rows padded to 80B (64B data + 16B) -> conflict-free ldmatrix.
#define ROWB 80
#define T_A 0
#define T_B 10240
#define STAGE 30720
#define NST 3
#define SMEM_GEMM (NST * STAGE)     // 92160
#define NTHR 256

__global__ void __launch_bounds__(NTHR, 1)
gemm_f16(const __half* __restrict__ A, long long sA, int lda,
         const __half* __restrict__ B, long long sB, int ldb,
         float* __restrict__ Cf, __half* __restrict__ Ch,
         long long sC, int ldc,
         const float* __restrict__ bias, int bias_mode,
         const float* __restrict__ resid, float alpha, int K) {
    extern __shared__ char smem[];
    const uint32_t sb = smem_u32(smem);
    const int tid = threadIdx.x;
    const int wid = tid >> 5, lane = tid & 31;
    const int wm = wid >> 2, wn = wid & 3;        // 2 x 4 warp grid
    const int bz = blockIdx.z;
    A += (size_t)bz * sA;
    B += (size_t)bz * sB;
    const size_t cOff = (size_t)bz * sC;
    const int m0 = blockIdx.y * 128;
    const int n0 = blockIdx.x * 256;

    float acc[4][8][4];
#pragma unroll
    for (int i = 0; i < 4; i++)
#pragma unroll
        for (int j = 0; j < 8; j++)
#pragma unroll
            for (int r = 0; r < 4; r++) acc[i][j][r] = 0.f;

    const int nch = K / 32;

    // ---- prologue: stages 0..NST-2 ----
#pragma unroll
    for (int s = 0; s < NST - 1; s++) {
        const uint32_t stg = sb + s * STAGE;
        const int k0 = s * 32;
#pragma unroll
        for (int i = 0; i < 2; i++) {   // A: 128 rows x 4 chunks = 512
            int idx = tid + i * NTHR;
            int row = idx >> 2, u = idx & 3;
            cpa16(stg + T_A + row * ROWB + u * 16,
                  A + (size_t)(m0 + row) * lda + k0 + u * 8);
        }
#pragma unroll
        for (int i = 0; i < 4; i++) {   // B: 256 rows x 4 chunks = 1024
            int idx = tid + i * NTHR;
            int row = idx >> 2, u = idx & 3;
            cpa16(stg + T_B + row * ROWB + u * 16,
                  B + (size_t)(n0 + row) * ldb + k0 + u * 8);
        }
        CP_COMMIT();
    }

    const int lr = lane & 15, lc = lane >> 4;                 // A frag addr
    const int nr = ((lane >> 4) << 3) | (lane & 7);           // B frag addr
    const int kc = (lane >> 3) & 1;

    uint32_t af[2][4][4], bf[2][4][4];   // double-buffered fragments

    for (int c = 0; c < nch; c++) {
        CP_WAIT(NST - 2);
        __syncthreads();
        // issue loads for stage c + NST - 1
        if (c + NST - 1 < nch) {
            const uint32_t stg = sb + ((c + NST - 1) % NST) * STAGE;
            const int k0 = (c + NST - 1) * 32;
#pragma unroll
            for (int i = 0; i < 2; i++) {
                int idx = tid + i * NTHR;
                int row = idx >> 2, u = idx & 3;
                cpa16(stg + T_A + row * ROWB + u * 16,
                      A + (size_t)(m0 + row) * lda + k0 + u * 8);
            }
#pragma unroll
            for (int i = 0; i < 4; i++) {
                int idx = tid + i * NTHR;
                int row = idx >> 2, u = idx & 3;
                cpa16(stg + T_B + row * ROWB + u * 16,
                      B + (size_t)(n0 + row) * ldb + k0 + u * 8);
            }
        }
        CP_COMMIT();

        const uint32_t stg = sb + (c % NST) * STAGE;
        // load fragments for k-group 0
#pragma unroll
        for (int mi = 0; mi < 4; mi++)
            LDSM4(af[0][mi], stg + T_A + (uint32_t)(wm * 64 + mi * 16 + lr) * ROWB
                             + lc * 16);
#pragma unroll
        for (int nt = 0; nt < 4; nt++)
            LDSM4(bf[0][nt], stg + T_B + (uint32_t)(wn * 64 + nt * 16 + nr) * ROWB
                             + kc * 16);
#pragma unroll
        for (int kk = 0; kk < 2; kk++) {
            if (kk == 0) {   // prefetch k-group 1 fragments
#pragma unroll
                for (int mi = 0; mi < 4; mi++)
                    LDSM4(af[1][mi], stg + T_A
                          + (uint32_t)(wm * 64 + mi * 16 + lr) * ROWB + lc * 16 + 32);
#pragma unroll
                for (int nt = 0; nt < 4; nt++)
                    LDSM4(bf[1][nt], stg + T_B
                          + (uint32_t)(wn * 64 + nt * 16 + nr) * ROWB + kc * 16 + 32);
            }
#pragma unroll
            for (int mi = 0; mi < 4; mi++)
#pragma unroll
                for (int nt = 0; nt < 4; nt++) {
                    MMA_F16(acc[mi][2 * nt + 0], af[kk][mi], bf[kk][nt]);
                    MMA_F16(acc[mi][2 * nt + 1], af[kk][mi], (bf[kk][nt] + 2));
                }
        }
    }

    // ---- epilogue ----
    const int r = lane >> 2;
    const int cb = 2 * (lane & 3);
#pragma unroll
    for (int mi = 0; mi < 4; mi++) {
#pragma unroll
        for (int h = 0; h < 2; h++) {
            const int m = m0 + wm * 64 + mi * 16 + h * 8 + r;
            const float bm = (bias_mode == 1) ? bias[m] : 0.f;
#pragma unroll
            for (int ni = 0; ni < 8; ni++) {
                const int n = n0 + wn * 64 + ni * 8 + cb;
                float v0 = acc[mi][ni][h * 2 + 0] * alpha + bm;
                float v1 = acc[mi][ni][h * 2 + 1] * alpha + bm;
                if (bias_mode == 2) { v0 += bias[n]; v1 += bias[n + 1]; }
                const size_t off = cOff + (size_t)m * ldc + n;
                if (Cf) {
                    if (resid) { v0 += resid[off]; v1 += resid[off + 1]; }
                    float2 o; o.x = v0; o.y = v1;
                    *(float2*)(Cf + off) = o;
                } else {
                    __half2 p;
                    p.x = __float2half(v0);
                    p.y = __float2half(v1);
                    *(__half2*)(Ch + off) = p;
                }
            }
        }
    }
}

// ---------------- launch -----------------------------------------------------
extern "C" void kernel_launch(void* const* d_in, const int* in_sizes, int n_in,
                              void* d_out, int out_size) {
    const float* x     = (const float*)d_in[0];
    const float* gamma = (const float*)d_in[1];
    const float* beta  = (const float*)d_in[2];
    const float* wq    = (const float*)d_in[3];
    const float* bq    = (const float*)d_in[4];
    const float* wk    = (const float*)d_in[5];
    const float* bk    = (const float*)d_in[6];
    const float* wv    = (const float*)d_in[7];
    const float* bv    = (const float*)d_in[8];
    const float* wo    = (const float*)d_in[9];
    const float* bo    = (const float*)d_in[10];
    float* out = (float*)d_out;

    cudaFuncSetAttribute(gemm_f16, cudaFuncAttributeMaxDynamicSharedMemorySize,
                         SMEM_GEMM);

    __half *hT, *w, *qkT, *v, *attn, *oT;
    float *S, *bqk;
    cudaGetSymbolAddress((void**)&hT, g_hT);
    cudaGetSymbolAddress((void**)&w, g_w);
    cudaGetSymbolAddress((void**)&bqk, g_bqk);
    cudaGetSymbolAddress((void**)&qkT, g_qkT);
    cudaGetSymbolAddress((void**)&v, g_v);
    cudaGetSymbolAddress((void**)&S, g_S);
    cudaGetSymbolAddress((void**)&attn, g_attn);
    cudaGetSymbolAddress((void**)&oT, g_oT);

    const float scale = 0.044194173824159216f;   // 512^-0.5
    const int WN = NCH * NCH;                    // 262144

    // 1) GroupNorm stats + normalize/transpose/convert
    gn_stats_kernel<<<NB * NGROUPS, 256>>>(x);
    gn_tr_kernel<<<dim3(NSP / 32, NCH / 32, NB), dim3(32, 8)>>>(x, gamma, beta);

    // 2) weight converts (one launch) + qk bias concat
    cvt4_kernel<<<WN / 256, 256>>>(wq, wk, wv, wo, bq, bk, w);

    // 3) fused qk proj: qkT[n, 0:1024] = hT[n,ci] . [wq;wk][co,ci]^T + bqk
    //    (M=4096, N=1024, K=512)
    gemm_f16<<<dim3(1024 / 256, NSP / 128, NB), NTHR, SMEM_GEMM>>>(
        hT, (long long)BCH_N, NCH, w, 0, NCH,
        nullptr, qkT, (long long)QK_N, 1024, bqk, 2, nullptr, 1.f, NCH);
    // v[c,n] = wv[c,ci] . hT[n,ci]^T + bv        (M=512, N=4096, K=512)
    gemm_f16<<<dim3(NSP / 256, NCH / 128, NB), NTHR, SMEM_GEMM>>>(
        w + 2 * WN, 0, NCH, hT, (long long)BCH_N, NCH,
        nullptr, v, (long long)BCH_N, NSP, bv, 1, nullptr, 1.f, NCH);

    // 4) S[i,j] = scale * q[i,c] . k[j,c]^T      (M=4096, N=4096, K=512)
    gemm_f16<<<dim3(NSP / 256, NSP / 128, NB), NTHR, SMEM_GEMM>>>(
        qkT, (long long)QK_N, 1024, qkT + NCH, (long long)QK_N, 1024,
        S, nullptr, (long long)ATT_N, NSP, nullptr, 0, nullptr, scale, NCH);

    // 5) softmax rows -> attn fp16
    softmax_kernel<<<NB * NSP, 256>>>(S);

    // 6) oT[i,c] = attn[i,j] . v[c,j]^T          (M=4096, N=512, K=4096)
    gemm_f16<<<dim3(NCH / 256, NSP / 128, NB), NTHR, SMEM_GEMM>>>(
        attn, (long long)ATT_N, NSP, v, (long long)BCH_N, NSP,
        nullptr, oT, (long long)BCH_N, NCH, nullptr, 0, nullptr, 1.f, NSP);

    // 7) out[c,n] = wo[c,ci] . oT[n,ci]^T + bo + x  (M=512, N=4096, K=512)
    gemm_f16<<<dim3(NSP / 256, NCH / 128, NB), NTHR, SMEM_GEMM>>>(
        w + 3 * WN, 0, NCH, oT, (long long)BCH_N, NCH,
        out, nullptr, (long long)BCH_N, NSP, bo, 1, x, 1.f, NCH);
}